// round 1
// baseline (speedup 1.0000x reference)
#include <cuda_runtime.h>
#include <cstdint>
#include <math.h>

#define BB    128
#define SSQ   256
#define LLC   16
#define EMB   256
#define HID   512
#define NCLS  20
#define CEMB  64
#define CHID  128
#define NW    (BB*SSQ)        // 32768 words
#define DIM   384             // EMB + CHID
#define G3C   384             // 3*CHID
#define G3H   1536            // 3*HID
#define WPB   16              // words per block in char GRU
#define NBLK_W 128            // persistent word-GRU blocks (<=148 SMs)

// ---------------- scratch (__device__ globals, no allocation) ----------------
__device__ float g_WiT[CEMB*G3C];        // char Wi^T [d][g]
__device__ float g_WhT[CHID*G3C];        // char Wh^T [j][g]
__device__ float g_gWiT[DIM*G3H];        // word Wi^T [d][g]
__device__ float g_charh[NW*CHID];       // char GRU final hidden, index n = s*B+b
__device__ float g_xw[(size_t)NW*G3H];   // word input projections [b*S+s][1536]
__device__ float g_hword[2*BB*HID];      // double-buffered word hidden
__device__ float g_gruout[(size_t)NW*HID];
__device__ unsigned int g_barArrive;
__device__ unsigned int g_barPhase;

// ---------------- kernel T: weight transposes ----------------
__global__ void k_transpose(const float* __restrict__ cWi,
                            const float* __restrict__ cWh,
                            const float* __restrict__ gWi) {
    int stride = gridDim.x * blockDim.x;
    int i0 = blockIdx.x * blockDim.x + threadIdx.x;
    for (int i = i0; i < G3C*CEMB; i += stride) {
        int g = i / CEMB, d = i % CEMB;
        g_WiT[d*G3C + g] = cWi[i];
    }
    for (int i = i0; i < G3C*CHID; i += stride) {
        int g = i / CHID, j = i % CHID;
        g_WhT[j*G3C + g] = cWh[i];
    }
    for (int i = i0; i < G3H*DIM; i += stride) {
        int g = i / DIM, d = i % DIM;
        g_gWiT[d*G3H + g] = gWi[i];
    }
}

// ---------------- kernel C: fused char GRU (16 words / block, 128 threads) ---
__global__ __launch_bounds__(128)
void k_chargru(const int* __restrict__ xc, const float* __restrict__ cembw,
               const float* __restrict__ cbi, const float* __restrict__ cbh) {
    extern __shared__ float sm[];
    float* s_cemb = sm;                         // [WPB][16][64]
    float* s_h    = sm + WPB*LLC*CEMB;          // [WPB][128]
    int*   s_ids  = (int*)(s_h + WPB*CHID);     // [WPB][16]
    const int tid = threadIdx.x;
    const int n0  = blockIdx.x * WPB;

    for (int i = tid; i < WPB*LLC; i += 128) s_ids[i] = xc[n0*LLC + i];
    __syncthreads();
    for (int i = tid; i < WPB*LLC*CEMB; i += 128) {
        int w = i >> 10, t = (i >> 6) & 15, d = i & 63;
        int c = s_ids[w*LLC + t];
        s_cemb[i] = cembw[c*CEMB + d];
    }
    for (int i = tid; i < WPB*CHID; i += 128) s_h[i] = 0.f;
    __syncthreads();

    const int gr = tid, gz = CHID + tid, gn = 2*CHID + tid;
    const float bR  = cbi[gr] + cbh[gr];
    const float bZ  = cbi[gz] + cbh[gz];
    const float bNx = cbi[gn];
    const float bNh = cbh[gn];

    for (int t = 0; t < LLC; t++) {
        float aR[WPB], aZ[WPB], aNx[WPB], aNh[WPB];
        #pragma unroll
        for (int w = 0; w < WPB; w++) { aR[w]=bR; aZ[w]=bZ; aNx[w]=bNx; aNh[w]=bNh; }

        const float* ce = s_cemb + t*CEMB;
        for (int d = 0; d < CEMB; d++) {
            float wr = g_WiT[d*G3C + gr];
            float wz = g_WiT[d*G3C + gz];
            float wn = g_WiT[d*G3C + gn];
            #pragma unroll
            for (int w = 0; w < WPB; w++) {
                float xv = ce[w*(LLC*CEMB) + d];
                aR[w]  = fmaf(xv, wr, aR[w]);
                aZ[w]  = fmaf(xv, wz, aZ[w]);
                aNx[w] = fmaf(xv, wn, aNx[w]);
            }
        }
        for (int j = 0; j < CHID; j++) {
            float wr = g_WhT[j*G3C + gr];
            float wz = g_WhT[j*G3C + gz];
            float wn = g_WhT[j*G3C + gn];
            #pragma unroll
            for (int w = 0; w < WPB; w++) {
                float hv = s_h[w*CHID + j];
                aR[w]  = fmaf(hv, wr, aR[w]);
                aZ[w]  = fmaf(hv, wz, aZ[w]);
                aNh[w] = fmaf(hv, wn, aNh[w]);
            }
        }
        __syncthreads();
        #pragma unroll
        for (int w = 0; w < WPB; w++) {
            float r  = 1.f / (1.f + expf(-aR[w]));
            float z  = 1.f / (1.f + expf(-aZ[w]));
            float nn = tanhf(aNx[w] + r*aNh[w]);
            float hp = s_h[w*CHID + tid];
            s_h[w*CHID + tid] = nn + z*(hp - nn);   // (1-z)n + z h
        }
        __syncthreads();
    }
    #pragma unroll
    for (int w = 0; w < WPB; w++)
        g_charh[(n0 + w)*CHID + tid] = s_h[w*CHID + tid];
}

// ---------------- kernel X: xw = feats @ gru_Wi^T + gru_bi (gather fused) ----
__global__ __launch_bounds__(256)
void k_xw(const int* __restrict__ xtok, const float* __restrict__ embw,
          const float* __restrict__ gbi) {
    __shared__ float As[16][68];
    __shared__ float Bs[16][68];
    const int tid = threadIdx.x;
    const int bn = blockIdx.x * 64;
    const int bm = blockIdx.y * 64;
    const int ty = tid >> 4, tx = tid & 15;

    float acc[4][4];
    #pragma unroll
    for (int i = 0; i < 4; i++)
        #pragma unroll
        for (int j = 0; j < 4; j++) acc[i][j] = 0.f;

    const int lr = tid >> 2;            // 0..63 (A row within tile)
    const int lc = (tid & 3) << 2;      // 0,4,8,12
    const int row = bm + lr;
    const int b = row >> 8, s = row & 255;
    const int tok = xtok[row];
    const int nidx = (s << 7) + b;      // char-hidden word index

    const int bkr = tid >> 4;           // 0..15 (B k-row)
    const int bnc = (tid & 15) << 2;    // 0..60

    for (int k0 = 0; k0 < DIM; k0 += 16) {
        const float* asrc = (k0 < EMB)
            ? (embw + (size_t)tok*EMB + k0 + lc)
            : (g_charh + (size_t)nidx*CHID + (k0 - EMB) + lc);
        float4 av = *(const float4*)asrc;
        As[lc+0][lr] = av.x; As[lc+1][lr] = av.y;
        As[lc+2][lr] = av.z; As[lc+3][lr] = av.w;
        *(float4*)&Bs[bkr][bnc] = *(const float4*)(g_gWiT + (size_t)(k0 + bkr)*G3H + bn + bnc);
        __syncthreads();
        #pragma unroll
        for (int k = 0; k < 16; k++) {
            float4 a4 = *(const float4*)&As[k][ty << 2];
            float4 b4 = *(const float4*)&Bs[k][tx << 2];
            float a[4] = {a4.x, a4.y, a4.z, a4.w};
            float bv[4] = {b4.x, b4.y, b4.z, b4.w};
            #pragma unroll
            for (int i = 0; i < 4; i++)
                #pragma unroll
                for (int j = 0; j < 4; j++)
                    acc[i][j] = fmaf(a[i], bv[j], acc[i][j]);
        }
        __syncthreads();
    }
    #pragma unroll
    for (int i = 0; i < 4; i++) {
        int r = bm + (ty << 2) + i;
        #pragma unroll
        for (int j = 0; j < 4; j++) {
            int c = bn + (tx << 2) + j;
            g_xw[(size_t)r*G3H + c] = acc[i][j] + gbi[c];
        }
    }
}

// ---------------- persistent word GRU ----------------
__device__ __forceinline__ void grid_barrier() {
    __threadfence();
    __syncthreads();
    if (threadIdx.x == 0) {
        volatile unsigned int* vph = &g_barPhase;
        unsigned int ph = *vph;
        unsigned int a = atomicAdd(&g_barArrive, 1u);
        if (a == NBLK_W - 1u) {
            g_barArrive = 0u;
            __threadfence();
            *vph = ph + 1u;
        } else {
            while (*vph == ph) { __nanosleep(100); }
        }
        __threadfence();
    }
    __syncthreads();
}

__device__ __forceinline__ float dot4(float4 a, float4 b, float c) {
    c = fmaf(a.x, b.x, c); c = fmaf(a.y, b.y, c);
    c = fmaf(a.z, b.z, c); c = fmaf(a.w, b.w, c);
    return c;
}

#define WBB 32      // batch rows per block
#define WJB 16      // hidden units per block
#define WST 516     // padded smem weight row stride (conflict-free float4)

__global__ __launch_bounds__(128, 1)
void k_wordgru(const float* __restrict__ gWh, const float* __restrict__ gbh) {
    extern __shared__ float sm[];
    float* sW = sm;                 // [48][516]  r/z/n weight columns for owned j's
    float* sH = sm + 48*WST;        // [32][512]  staged hidden
    const int tid = threadIdx.x;
    const int bid = blockIdx.x;
    const int jc = bid & 31, bc = bid >> 5;
    const int j0 = jc * WJB, b0 = bc * WBB;
    const int jl = tid & 15;
    const int bq = tid >> 4;        // 0..7
    const int bl0 = bq * 4;

    // stage recurrent weights once (reused over all 256 steps)
    for (int i = tid; i < 48*HID; i += 128) {
        int gl = i >> 9, k = i & 511;
        int gate = gl >> 4, jj = gl & 15;
        int g = gate*HID + j0 + jj;
        sW[gl*WST + k] = gWh[(size_t)g*HID + k];
    }
    const float bhR = gbh[j0 + jl];
    const float bhZ = gbh[HID + j0 + jl];
    const float bhN = gbh[2*HID + j0 + jl];
    for (int i = tid; i < WBB*HID; i += 128) sH[i] = 0.f;  // h0 = 0
    __syncthreads();

    const float4* wR = (const float4*)(sW + (0*16 + jl)*WST);
    const float4* wZ = (const float4*)(sW + (16  + jl)*WST);
    const float4* wN = (const float4*)(sW + (32  + jl)*WST);
    const int j = j0 + jl;

    for (int s = 0; s < SSQ; s++) {
        float aR[4], aZ[4], aNh[4];
        #pragma unroll
        for (int q = 0; q < 4; q++) { aR[q]=bhR; aZ[q]=bhZ; aNh[q]=bhN; }

        const float4* h0p = (const float4*)(sH + (bl0+0)*HID);
        const float4* h1p = (const float4*)(sH + (bl0+1)*HID);
        const float4* h2p = (const float4*)(sH + (bl0+2)*HID);
        const float4* h3p = (const float4*)(sH + (bl0+3)*HID);
        #pragma unroll 4
        for (int k4 = 0; k4 < HID/4; k4++) {
            float4 r4 = wR[k4], z4 = wZ[k4], n4 = wN[k4];
            float4 h0 = h0p[k4], h1 = h1p[k4], h2 = h2p[k4], h3 = h3p[k4];
            aR[0]=dot4(h0,r4,aR[0]); aZ[0]=dot4(h0,z4,aZ[0]); aNh[0]=dot4(h0,n4,aNh[0]);
            aR[1]=dot4(h1,r4,aR[1]); aZ[1]=dot4(h1,z4,aZ[1]); aNh[1]=dot4(h1,n4,aNh[1]);
            aR[2]=dot4(h2,r4,aR[2]); aZ[2]=dot4(h2,z4,aZ[2]); aNh[2]=dot4(h2,n4,aNh[2]);
            aR[3]=dot4(h3,r4,aR[3]); aZ[3]=dot4(h3,z4,aZ[3]); aNh[3]=dot4(h3,n4,aNh[3]);
        }

        float* hOut = g_hword + ((s + 1) & 1) * (BB*HID);   // double buffer
        #pragma unroll
        for (int q = 0; q < 4; q++) {
            int b = b0 + bl0 + q;
            size_t base = ((size_t)b*SSQ + s) * G3H;
            float xr = g_xw[base + j];
            float xz = g_xw[base + HID + j];
            float xn = g_xw[base + 2*HID + j];
            float r  = 1.f / (1.f + expf(-(xr + aR[q])));
            float z  = 1.f / (1.f + expf(-(xz + aZ[q])));
            float nn = tanhf(xn + r*aNh[q]);
            float hp = sH[(bl0+q)*HID + j];
            float hn = nn + z*(hp - nn);
            hOut[b*HID + j] = hn;
            g_gruout[((size_t)b*SSQ + s)*HID + j] = hn;
        }
        if (s == SSQ - 1) break;
        grid_barrier();
        const float* hIn = g_hword + ((s + 1) & 1) * (BB*HID);
        for (int i = tid; i < WBB*HID; i += 128) {
            int bl = i >> 9, k = i & 511;
            sH[i] = hIn[(b0 + bl)*HID + k];
        }
        __syncthreads();
    }
}

// ---------------- classifier ----------------
__global__ __launch_bounds__(256)
void k_cls(const float* __restrict__ clsW, const float* __restrict__ clsb,
           float* __restrict__ out) {
    const int warp = threadIdx.x >> 5, lane = threadIdx.x & 31;
    const int gw = blockIdx.x * 8 + warp;
    for (int row = gw; row < NW; row += gridDim.x * 8) {
        const float* hrow = g_gruout + (size_t)row * HID;
        float acc[NCLS];
        #pragma unroll
        for (int c = 0; c < NCLS; c++) acc[c] = 0.f;
        for (int k = lane; k < HID; k += 32) {
            float hv = hrow[k];
            #pragma unroll
            for (int c = 0; c < NCLS; c++)
                acc[c] = fmaf(hv, clsW[c*HID + k], acc[c]);
        }
        #pragma unroll
        for (int off = 16; off > 0; off >>= 1) {
            #pragma unroll
            for (int c = 0; c < NCLS; c++)
                acc[c] += __shfl_down_sync(0xffffffffu, acc[c], off);
        }
        if (lane == 0) {
            #pragma unroll
            for (int c = 0; c < NCLS; c++)
                out[(size_t)row*NCLS + c] = acc[c] + clsb[c];
        }
    }
}

// ---------------- launch ----------------
extern "C" void kernel_launch(void* const* d_in, const int* in_sizes, int n_in,
                              void* d_out, int out_size) {
    const int*   x     = (const int*)  d_in[0];
    const int*   xch   = (const int*)  d_in[1];
    const float* embw  = (const float*)d_in[2];
    const float* cembw = (const float*)d_in[3];
    const float* cWi   = (const float*)d_in[4];
    const float* cWh   = (const float*)d_in[5];
    const float* cbi   = (const float*)d_in[6];
    const float* cbh   = (const float*)d_in[7];
    const float* gWi   = (const float*)d_in[8];
    const float* gWh   = (const float*)d_in[9];
    const float* gbi   = (const float*)d_in[10];
    const float* gbh   = (const float*)d_in[11];
    const float* clsW  = (const float*)d_in[12];
    const float* clsb  = (const float*)d_in[13];
    float* out = (float*)d_out;

    const int csmem = (WPB*LLC*CEMB + WPB*CHID) * 4 + WPB*LLC * 4;  // 74752 B
    const int wsmem = (48*WST + WBB*HID) * 4;                        // 164608 B
    cudaFuncSetAttribute(k_chargru, cudaFuncAttributeMaxDynamicSharedMemorySize, csmem);
    cudaFuncSetAttribute(k_wordgru, cudaFuncAttributeMaxDynamicSharedMemorySize, wsmem);

    k_transpose<<<256, 256>>>(cWi, cWh, gWi);
    k_chargru<<<NW/WPB, 128, csmem>>>(xch, cembw, cbi, cbh);
    dim3 gx(G3H/64, NW/64);
    k_xw<<<gx, 256>>>(x, embw, gbi);
    k_wordgru<<<NBLK_W, 128, wsmem>>>(gWh, gbh);
    k_cls<<<512, 256>>>(clsW, clsb, out);
}

// round 3
// speedup vs baseline: 1.5350x; 1.5350x over previous
#include <cuda_runtime.h>
#include <cstdint>
#include <math.h>

#define BB    128
#define SSQ   256
#define LLC   16
#define EMB   256
#define HID   512
#define NCLS  20
#define CEMB  64
#define CHID  128
#define NW    (BB*SSQ)        // 32768 words
#define DIM   384             // EMB + CHID
#define G3C   384             // 3*CHID
#define G3H   1536            // 3*HID
#define NBLK_W 128            // persistent word-GRU blocks (<=148 SMs)

// ---------------- scratch (__device__ globals, no allocation) ----------------
__device__ float g_WiT[CEMB*G3C];                 // char Wi^T [d][g]
__device__ float g_WhT[CHID*G3C];                 // char Wh^T [j][g]
__device__ float g_gWiT[DIM*G3H];                 // word Wi^T [d][g]
__device__ float g_cxw[(size_t)NW*LLC*G3C];       // char input projections [n*16+t][384]
__device__ float g_charh[NW*CHID];                // char GRU final hidden, index n = s*B+b
__device__ float g_xw[(size_t)NW*G3H];            // word input projections [b*S+s][1536]
__device__ float g_hword[2*BB*HID];               // double-buffered word hidden
__device__ float g_gruout[(size_t)NW*HID];
__device__ unsigned int g_barArrive;
__device__ unsigned int g_barPhase;

// ---------------- kernel T: weight transposes ----------------
__global__ void k_transpose(const float* __restrict__ cWi,
                            const float* __restrict__ cWh,
                            const float* __restrict__ gWi) {
    int stride = gridDim.x * blockDim.x;
    int i0 = blockIdx.x * blockDim.x + threadIdx.x;
    for (int i = i0; i < G3C*CEMB; i += stride) {
        int g = i / CEMB, d = i % CEMB;
        g_WiT[d*G3C + g] = cWi[i];
    }
    for (int i = i0; i < G3C*CHID; i += stride) {
        int g = i / CHID, j = i % CHID;
        g_WhT[j*G3C + g] = cWh[i];
    }
    for (int i = i0; i < G3H*DIM; i += stride) {
        int g = i / DIM, d = i % DIM;
        g_gWiT[d*G3H + g] = gWi[i];
    }
}

// ---------------- kernel CX: cxw = gather(cemb) @ WiT + cbi ------------------
// 128x64 tile, 256 threads, 8x4 microtile, K=64.
__global__ __launch_bounds__(256)
void k_cxw(const int* __restrict__ xc, const float* __restrict__ cembw,
           const float* __restrict__ cbi) {
    __shared__ float As[16][132];
    __shared__ float Bs[16][68];
    __shared__ int   sId[128];
    const int tid = threadIdx.x;
    const int bm = blockIdx.y * 128;
    const int bn = blockIdx.x * 64;
    if (tid < 128) sId[tid] = xc[bm + tid];
    __syncthreads();

    const int ar = tid >> 1, ak = (tid & 1) * 8;
    const int ty = tid >> 4, tx = tid & 15;
    const int bk = tid >> 4, bc = (tid & 15) * 4;
    const float* arow = cembw + (size_t)sId[ar] * CEMB;

    float acc[8][4];
    #pragma unroll
    for (int i = 0; i < 8; i++)
        #pragma unroll
        for (int j = 0; j < 4; j++) acc[i][j] = 0.f;

    for (int k0 = 0; k0 < CEMB; k0 += 16) {
        #pragma unroll
        for (int i = 0; i < 2; i++) {
            float4 v = *(const float4*)(arow + k0 + ak + i*4);
            As[ak+i*4+0][ar] = v.x; As[ak+i*4+1][ar] = v.y;
            As[ak+i*4+2][ar] = v.z; As[ak+i*4+3][ar] = v.w;
        }
        *(float4*)&Bs[bk][bc] = *(const float4*)(g_WiT + (size_t)(k0 + bk)*G3C + bn + bc);
        __syncthreads();
        #pragma unroll
        for (int k = 0; k < 16; k++) {
            float4 a0 = *(const float4*)&As[k][ty*8];
            float4 a1 = *(const float4*)&As[k][ty*8+4];
            float4 b4 = *(const float4*)&Bs[k][tx*4];
            float a[8] = {a0.x,a0.y,a0.z,a0.w,a1.x,a1.y,a1.z,a1.w};
            float bv[4] = {b4.x,b4.y,b4.z,b4.w};
            #pragma unroll
            for (int i = 0; i < 8; i++)
                #pragma unroll
                for (int j = 0; j < 4; j++)
                    acc[i][j] = fmaf(a[i], bv[j], acc[i][j]);
        }
        __syncthreads();
    }
    #pragma unroll
    for (int i = 0; i < 8; i++) {
        size_t r = bm + ty*8 + i;
        #pragma unroll
        for (int j = 0; j < 4; j++) {
            int c = bn + tx*4 + j;
            g_cxw[r*G3C + c] = acc[i][j] + cbi[c];
        }
    }
}

// ---------------- kernel CR: char GRU recurrent (WhT fully in smem) ----------
// 256 threads: j = tid&127, half = tid>>7. 16 words/block, 8 per half.
#define CR_WPB 16
__global__ __launch_bounds__(256, 1)
void k_charrec(const float* __restrict__ cbh) {
    extern __shared__ float sm[];
    float* sW = sm;                      // [128][384]
    float* sH = sm + CHID*G3C;           // [16][128]
    const int tid = threadIdx.x;
    const int j = tid & 127;
    const int half = tid >> 7;
    const int n0 = blockIdx.x * CR_WPB;

    {
        const float4* src = (const float4*)g_WhT;
        float4* dst = (float4*)sW;
        for (int i = tid; i < CHID*G3C/4; i += 256) dst[i] = src[i];
        float4 z4 = make_float4(0.f,0.f,0.f,0.f);
        float4* h4 = (float4*)sH;
        for (int i = tid; i < CR_WPB*CHID/4; i += 256) h4[i] = z4;
    }
    const float bR = cbh[j], bZ = cbh[CHID + j], bN = cbh[2*CHID + j];
    __syncthreads();

    for (int t = 0; t < LLC; t++) {
        float xr[8], xz[8], xn[8];
        #pragma unroll
        for (int q = 0; q < 8; q++) {
            size_t rr = ((size_t)(n0 + half*8 + q)*LLC + t)*G3C;
            xr[q] = g_cxw[rr + j];
            xz[q] = g_cxw[rr + CHID + j];
            xn[q] = g_cxw[rr + 2*CHID + j];
        }
        float aR[8], aZ[8], aN[8];
        #pragma unroll
        for (int q = 0; q < 8; q++) { aR[q]=bR; aZ[q]=bZ; aN[q]=bN; }

        #pragma unroll 2
        for (int i = 0; i < CHID; i++) {
            float wr = sW[i*G3C + j];
            float wz = sW[i*G3C + CHID + j];
            float wn = sW[i*G3C + 2*CHID + j];
            const float* hrow = sH + half*8*CHID + i;
            #pragma unroll
            for (int q = 0; q < 8; q++) {
                float hv = hrow[q*CHID];
                aR[q] = fmaf(hv, wr, aR[q]);
                aZ[q] = fmaf(hv, wz, aZ[q]);
                aN[q] = fmaf(hv, wn, aN[q]);
            }
        }
        __syncthreads();
        #pragma unroll
        for (int q = 0; q < 8; q++) {
            int w = half*8 + q;
            float r  = 1.f / (1.f + expf(-(xr[q] + aR[q])));
            float z  = 1.f / (1.f + expf(-(xz[q] + aZ[q])));
            float nn = tanhf(xn[q] + r*aN[q]);
            float hp = sH[w*CHID + j];
            sH[w*CHID + j] = nn + z*(hp - nn);
        }
        __syncthreads();
    }
    #pragma unroll
    for (int q = 0; q < 8; q++) {
        int w = half*8 + q;
        g_charh[(size_t)(n0 + w)*CHID + j] = sH[w*CHID + j];
    }
}

// ---------------- kernel X: xw = [emb||charh] @ gWiT + gbi -------------------
// 128x64 tile, 256 threads, 8x4 microtile, K=384, gather fused.
__global__ __launch_bounds__(256)
void k_xw(const int* __restrict__ xtok, const float* __restrict__ embw,
          const float* __restrict__ gbi) {
    __shared__ float As[16][132];
    __shared__ float Bs[16][68];
    __shared__ int   sTok[128];
    const int tid = threadIdx.x;
    const int bm = blockIdx.y * 128;
    const int bn = blockIdx.x * 64;
    if (tid < 128) sTok[tid] = xtok[bm + tid];
    __syncthreads();

    const int ar = tid >> 1, ak = (tid & 1) * 8;
    const int ty = tid >> 4, tx = tid & 15;
    const int bk = tid >> 4, bc = (tid & 15) * 4;
    const int r = bm + ar;
    const float* aEmb = embw + (size_t)sTok[ar]*EMB;
    const float* aChr = g_charh + (size_t)((r & 255)*128 + (r >> 8))*CHID;

    float acc[8][4];
    #pragma unroll
    for (int i = 0; i < 8; i++)
        #pragma unroll
        for (int j = 0; j < 4; j++) acc[i][j] = 0.f;

    for (int k0 = 0; k0 < DIM; k0 += 16) {
        const float* src = (k0 < EMB) ? (aEmb + k0) : (aChr + (k0 - EMB));
        #pragma unroll
        for (int i = 0; i < 2; i++) {
            float4 v = *(const float4*)(src + ak + i*4);
            As[ak+i*4+0][ar] = v.x; As[ak+i*4+1][ar] = v.y;
            As[ak+i*4+2][ar] = v.z; As[ak+i*4+3][ar] = v.w;
        }
        *(float4*)&Bs[bk][bc] = *(const float4*)(g_gWiT + (size_t)(k0 + bk)*G3H + bn + bc);
        __syncthreads();
        #pragma unroll
        for (int k = 0; k < 16; k++) {
            float4 a0 = *(const float4*)&As[k][ty*8];
            float4 a1 = *(const float4*)&As[k][ty*8+4];
            float4 b4 = *(const float4*)&Bs[k][tx*4];
            float a[8] = {a0.x,a0.y,a0.z,a0.w,a1.x,a1.y,a1.z,a1.w};
            float bv[4] = {b4.x,b4.y,b4.z,b4.w};
            #pragma unroll
            for (int i = 0; i < 8; i++)
                #pragma unroll
                for (int j = 0; j < 4; j++)
                    acc[i][j] = fmaf(a[i], bv[j], acc[i][j]);
        }
        __syncthreads();
    }
    #pragma unroll
    for (int i = 0; i < 8; i++) {
        size_t rr = bm + ty*8 + i;
        #pragma unroll
        for (int j = 0; j < 4; j++) {
            int c = bn + tx*4 + j;
            g_xw[rr*G3H + c] = acc[i][j] + gbi[c];
        }
    }
}

// ---------------- persistent word GRU ----------------
__device__ __forceinline__ void grid_barrier() {
    __threadfence();
    __syncthreads();
    if (threadIdx.x == 0) {
        volatile unsigned int* vph = &g_barPhase;
        unsigned int ph = *vph;
        unsigned int a = atomicAdd(&g_barArrive, 1u);
        if (a == NBLK_W - 1u) {
            g_barArrive = 0u;
            __threadfence();
            *vph = ph + 1u;
        } else {
            while (*vph == ph) { __nanosleep(20); }
        }
        __threadfence();
    }
    __syncthreads();
}

__device__ __forceinline__ float dot4(float4 a, float4 b, float c) {
    c = fmaf(a.x, b.x, c); c = fmaf(a.y, b.y, c);
    c = fmaf(a.z, b.z, c); c = fmaf(a.w, b.w, c);
    return c;
}

#define WBB 32      // batch rows per block
#define WJB 16      // hidden units per block
#define WST 516     // padded smem weight row stride

__global__ __launch_bounds__(128, 1)
void k_wordgru(const float* __restrict__ gWh, const float* __restrict__ gbh) {
    extern __shared__ float sm[];
    float* sW = sm;                 // [48][516]
    float* sH = sm + 48*WST;        // [32][512]
    const int tid = threadIdx.x;
    const int bid = blockIdx.x;
    const int jc = bid & 31, bc = bid >> 5;
    const int j0 = jc * WJB, b0 = bc * WBB;
    const int jl = tid & 15;
    const int bq = tid >> 4;        // 0..7
    const int bl0 = bq * 4;

    for (int i = tid; i < 48*HID; i += 128) {
        int gl = i >> 9, k = i & 511;
        int gate = gl >> 4, jj = gl & 15;
        int g = gate*HID + j0 + jj;
        sW[gl*WST + k] = gWh[(size_t)g*HID + k];
    }
    const float bhR = gbh[j0 + jl];
    const float bhZ = gbh[HID + j0 + jl];
    const float bhN = gbh[2*HID + j0 + jl];
    {
        float4 z4 = make_float4(0.f,0.f,0.f,0.f);
        float4* h4 = (float4*)sH;
        for (int i = tid; i < WBB*HID/4; i += 128) h4[i] = z4;
    }
    __syncthreads();

    const float4* wR = (const float4*)(sW + (0*16 + jl)*WST);
    const float4* wZ = (const float4*)(sW + (16  + jl)*WST);
    const float4* wN = (const float4*)(sW + (32  + jl)*WST);
    const int j = j0 + jl;

    for (int s = 0; s < SSQ; s++) {
        // prefetch xw for this step (independent of h; hides DRAM latency
        // under the ~12k-cycle dot loop)
        float xr[4], xz[4], xn[4];
        #pragma unroll
        for (int q = 0; q < 4; q++) {
            size_t base = ((size_t)(b0 + bl0 + q)*SSQ + s) * G3H;
            xr[q] = g_xw[base + j];
            xz[q] = g_xw[base + HID + j];
            xn[q] = g_xw[base + 2*HID + j];
        }

        float aR[4], aZ[4], aNh[4];
        #pragma unroll
        for (int q = 0; q < 4; q++) { aR[q]=bhR; aZ[q]=bhZ; aNh[q]=bhN; }

        const float4* h0p = (const float4*)(sH + (bl0+0)*HID);
        const float4* h1p = (const float4*)(sH + (bl0+1)*HID);
        const float4* h2p = (const float4*)(sH + (bl0+2)*HID);
        const float4* h3p = (const float4*)(sH + (bl0+3)*HID);
        #pragma unroll 4
        for (int k4 = 0; k4 < HID/4; k4++) {
            float4 r4 = wR[k4], z4 = wZ[k4], n4 = wN[k4];
            float4 h0 = h0p[k4], h1 = h1p[k4], h2 = h2p[k4], h3 = h3p[k4];
            aR[0]=dot4(h0,r4,aR[0]); aZ[0]=dot4(h0,z4,aZ[0]); aNh[0]=dot4(h0,n4,aNh[0]);
            aR[1]=dot4(h1,r4,aR[1]); aZ[1]=dot4(h1,z4,aZ[1]); aNh[1]=dot4(h1,n4,aNh[1]);
            aR[2]=dot4(h2,r4,aR[2]); aZ[2]=dot4(h2,z4,aZ[2]); aNh[2]=dot4(h2,n4,aNh[2]);
            aR[3]=dot4(h3,r4,aR[3]); aZ[3]=dot4(h3,z4,aZ[3]); aNh[3]=dot4(h3,n4,aNh[3]);
        }

        float* hOut = g_hword + ((s + 1) & 1) * (BB*HID);
        #pragma unroll
        for (int q = 0; q < 4; q++) {
            int b = b0 + bl0 + q;
            float r  = 1.f / (1.f + expf(-(xr[q] + aR[q])));
            float z  = 1.f / (1.f + expf(-(xz[q] + aZ[q])));
            float nn = tanhf(xn[q] + r*aNh[q]);
            float hp = sH[(bl0+q)*HID + j];
            float hn = nn + z*(hp - nn);
            hOut[b*HID + j] = hn;
            g_gruout[((size_t)b*SSQ + s)*HID + j] = hn;
        }
        if (s == SSQ - 1) break;
        grid_barrier();
        const float4* hIn4 = (const float4*)(g_hword + ((s + 1) & 1) * (BB*HID) + b0*HID);
        float4* sH4 = (float4*)sH;
        for (int i = tid; i < WBB*HID/4; i += 128) sH4[i] = hIn4[i];
        __syncthreads();
    }
}

// ---------------- classifier ----------------
__global__ __launch_bounds__(256)
void k_cls(const float* __restrict__ clsW, const float* __restrict__ clsb,
           float* __restrict__ out) {
    const int warp = threadIdx.x >> 5, lane = threadIdx.x & 31;
    const int gw = blockIdx.x * 8 + warp;
    for (int row = gw; row < NW; row += gridDim.x * 8) {
        const float* hrow = g_gruout + (size_t)row * HID;
        float acc[NCLS];
        #pragma unroll
        for (int c = 0; c < NCLS; c++) acc[c] = 0.f;
        for (int k = lane; k < HID; k += 32) {
            float hv = hrow[k];
            #pragma unroll
            for (int c = 0; c < NCLS; c++)
                acc[c] = fmaf(hv, clsW[c*HID + k], acc[c]);
        }
        #pragma unroll
        for (int off = 16; off > 0; off >>= 1) {
            #pragma unroll
            for (int c = 0; c < NCLS; c++)
                acc[c] += __shfl_down_sync(0xffffffffu, acc[c], off);
        }
        if (lane == 0) {
            #pragma unroll
            for (int c = 0; c < NCLS; c++)
                out[(size_t)row*NCLS + c] = acc[c] + clsb[c];
        }
    }
}

// ---------------- launch ----------------
extern "C" void kernel_launch(void* const* d_in, const int* in_sizes, int n_in,
                              void* d_out, int out_size) {
    const int*   x     = (const int*)  d_in[0];
    const int*   xch   = (const int*)  d_in[1];
    const float* embw  = (const float*)d_in[2];
    const float* cembw = (const float*)d_in[3];
    const float* cWi   = (const float*)d_in[4];
    const float* cWh   = (const float*)d_in[5];
    const float* cbi   = (const float*)d_in[6];
    const float* cbh   = (const float*)d_in[7];
    const float* gWi   = (const float*)d_in[8];
    const float* gWh   = (const float*)d_in[9];
    const float* gbi   = (const float*)d_in[10];
    const float* gbh   = (const float*)d_in[11];
    const float* clsW  = (const float*)d_in[12];
    const float* clsb  = (const float*)d_in[13];
    float* out = (float*)d_out;

    const int crsmem = (CHID*G3C + CR_WPB*CHID) * 4;   // 204800 B
    const int wsmem  = (48*WST + WBB*HID) * 4;         // 164608 B
    cudaFuncSetAttribute(k_charrec, cudaFuncAttributeMaxDynamicSharedMemorySize, crsmem);
    cudaFuncSetAttribute(k_wordgru, cudaFuncAttributeMaxDynamicSharedMemorySize, wsmem);

    k_transpose<<<256, 256>>>(cWi, cWh, gWi);
    dim3 gcx(G3C/64, NW*LLC/128);                      // (6, 4096)
    k_cxw<<<gcx, 256>>>(xch, cembw, cbi);
    k_charrec<<<NW/CR_WPB, 256, crsmem>>>(cbh);
    dim3 gx(G3H/64, NW/128);                           // (24, 256)
    k_xw<<<gx, 256>>>(x, embw, gbi);
    k_wordgru<<<NBLK_W, 128, wsmem>>>(gWh, gbh);
    k_cls<<<512, 256>>>(clsW, clsb, out);
}

// round 6
// speedup vs baseline: 1.6967x; 1.1054x over previous
#include <cuda_runtime.h>
#include <cuda_bf16.h>
#include <mma.h>
#include <cstdint>
#include <math.h>

using namespace nvcuda;

#define BB    128
#define SSQ   256
#define LLC   16
#define EMB   256
#define HID   512
#define NCLS  20
#define CEMB  64
#define CHID  128
#define NW    (BB*SSQ)        // 32768 words
#define DIM   384             // EMB + CHID
#define G3C   384             // 3*CHID
#define G3H   1536            // 3*HID
#define NBLK_W 128

// ---------------- scratch (__device__ globals, no allocation) ----------------
__device__ float g_WhT[CHID*G3C];                 // char Wh^T [j][g]
__device__ float g_cxw[(size_t)NW*LLC*G3C];       // char input projections
__device__ float g_charh[NW*CHID];                // char GRU final hidden (n = s*B+b)
__device__ float g_xw[(size_t)NW*G3H];            // word input projections
__device__ float g_hword[2*BB*HID];
__device__ float g_gruout[(size_t)NW*HID];
__device__ unsigned int g_barArrive;
__device__ unsigned int g_barPhase;
// split-bf16 weights (row-major [N][K])
__device__ __nv_bfloat16 g_BxwHi[G3H*DIM],  g_BxwLo[G3H*DIM];
__device__ __nv_bfloat16 g_BcxHi[G3C*CEMB], g_BcxLo[G3C*CEMB];
// split-bf16 gathered A matrices
__device__ __nv_bfloat16 g_AcH[(size_t)NW*LLC*CEMB], g_AcL[(size_t)NW*LLC*CEMB];
__device__ __nv_bfloat16 g_AxH[(size_t)NW*DIM],      g_AxL[(size_t)NW*DIM];

// ---------------- helpers ----------------
__device__ __forceinline__ void cvtf4(float4 v, uint2& hi, uint2& lo) {
    __nv_bfloat16 hx = __float2bfloat16(v.x), hy = __float2bfloat16(v.y);
    __nv_bfloat16 hz = __float2bfloat16(v.z), hw = __float2bfloat16(v.w);
    float lx = v.x - __bfloat162float(hx), ly = v.y - __bfloat162float(hy);
    float lz = v.z - __bfloat162float(hz), lw = v.w - __bfloat162float(hw);
    union { __nv_bfloat162 b; uint32_t u; } a0, a1, b0, b1;
    a0.b = __halves2bfloat162(hx, hy);  a1.b = __halves2bfloat162(hz, hw);
    b0.b = __halves2bfloat162(__float2bfloat16(lx), __float2bfloat16(ly));
    b1.b = __halves2bfloat162(__float2bfloat16(lz), __float2bfloat16(lw));
    hi = make_uint2(a0.u, a1.u);
    lo = make_uint2(b0.u, b1.u);
}

// ---------------- kernel P: weight prep ----------------
__global__ void k_prep(const float* __restrict__ cWh, const float* __restrict__ gWi,
                       const float* __restrict__ cWi) {
    int stride = gridDim.x * blockDim.x;
    int i0 = blockIdx.x * blockDim.x + threadIdx.x;
    for (int i = i0; i < G3C*CHID; i += stride) {
        int g = i / CHID, j = i % CHID;
        g_WhT[j*G3C + g] = cWh[i];
    }
    for (int i = i0; i < G3H*DIM; i += stride) {
        float v = gWi[i];
        __nv_bfloat16 h = __float2bfloat16(v);
        g_BxwHi[i] = h;
        g_BxwLo[i] = __float2bfloat16(v - __bfloat162float(h));
    }
    for (int i = i0; i < G3C*CEMB; i += stride) {
        float v = cWi[i];
        __nv_bfloat16 h = __float2bfloat16(v);
        g_BcxHi[i] = h;
        g_BcxLo[i] = __float2bfloat16(v - __bfloat162float(h));
    }
}

// ---------------- gather A for char GEMM: [524288][64] hi/lo -----------------
__global__ __launch_bounds__(256)
void k_gatherA_c(const int* __restrict__ xc, const float* __restrict__ cembw) {
    const int r = blockIdx.x * 256 + threadIdx.x;   // 0..524287
    const int c = xc[r];
    const float4* src = (const float4*)(cembw + (size_t)c * CEMB);
    uint2* dh = (uint2*)(g_AcH + (size_t)r * CEMB);
    uint2* dl = (uint2*)(g_AcL + (size_t)r * CEMB);
    #pragma unroll
    for (int i = 0; i < 16; i++) {
        uint2 hi, lo;
        cvtf4(src[i], hi, lo);
        dh[i] = hi; dl[i] = lo;
    }
}

// ---------------- gather A for word GEMM: [32768][384] hi/lo -----------------
__global__ __launch_bounds__(256)
void k_gatherA_x(const int* __restrict__ xtok, const float* __restrict__ embw) {
    const int warp = threadIdx.x >> 5, lane = threadIdx.x & 31;
    const int row = blockIdx.x * 8 + warp;
    const int tok = xtok[row];
    const int nidx = (row & 255) * 128 + (row >> 8);
    uint2* dh = (uint2*)(g_AxH + (size_t)row * DIM);
    uint2* dl = (uint2*)(g_AxL + (size_t)row * DIM);
    #pragma unroll
    for (int q = 0; q < 3; q++) {
        int k4 = q * 32 + lane;          // float4 index, 0..95
        int k = k4 * 4;
        float4 v = (k < EMB)
            ? *(const float4*)(embw + (size_t)tok * EMB + k)
            : *(const float4*)(g_charh + (size_t)nidx * CHID + (k - EMB));
        uint2 hi, lo;
        cvtf4(v, hi, lo);
        dh[k4] = hi; dl[k4] = lo;
    }
}

// ---------------- wmma split-bf16 GEMM: C = A·B^T + bias ---------------------
// BM=128, BN=64, BK=64. 256 threads = 8 warps (4m x 2n), warp tile 32x32.
#define GPAD 72
#define GSM_A  (128*GPAD)                // elems
#define GSM_B  (64*GPAD)
#define GEMM_SMEM ((2*GSM_A + 2*GSM_B) * 2)   // bytes = 55296

__global__ __launch_bounds__(256)
void k_gemm(const __nv_bfloat16* __restrict__ Ah, const __nv_bfloat16* __restrict__ Al,
            const __nv_bfloat16* __restrict__ Bh, const __nv_bfloat16* __restrict__ Bl,
            const float* __restrict__ bias, float* __restrict__ C,
            int N, int K) {
    extern __shared__ char smraw[];
    __nv_bfloat16* sAh = (__nv_bfloat16*)smraw;
    __nv_bfloat16* sAl = sAh + GSM_A;
    __nv_bfloat16* sBh = sAl + GSM_A;
    __nv_bfloat16* sBl = sBh + GSM_B;
    float* sC = (float*)smraw;           // reused in epilogue (128x68)

    const int tid = threadIdx.x;
    const int warp = tid >> 5;
    const int wm = warp & 3, wn = warp >> 2;
    const int bm = blockIdx.y * 128, bn = blockIdx.x * 64;

    wmma::fragment<wmma::accumulator, 16, 16, 16, float> acc[2][2];
    #pragma unroll
    for (int i = 0; i < 2; i++)
        #pragma unroll
        for (int j = 0; j < 2; j++) wmma::fill_fragment(acc[i][j], 0.f);

    for (int k0 = 0; k0 < K; k0 += 64) {
        // A tiles: 128 rows x 8 uint4 per matrix; 4 uint4 per thread each
        #pragma unroll
        for (int q = 0; q < 4; q++) {
            int j = tid * 4 + q;
            int r = j >> 3, c8 = j & 7;
            const uint4* sh = (const uint4*)(Ah + (size_t)(bm + r) * K + k0);
            const uint4* sl = (const uint4*)(Al + (size_t)(bm + r) * K + k0);
            *(uint4*)(sAh + r*GPAD + c8*8) = sh[c8];
            *(uint4*)(sAl + r*GPAD + c8*8) = sl[c8];
        }
        // B tiles: 64 rows x 8 uint4; 2 per thread each
        #pragma unroll
        for (int q = 0; q < 2; q++) {
            int j = tid * 2 + q;
            int r = j >> 3, c8 = j & 7;
            const uint4* sh = (const uint4*)(Bh + (size_t)(bn + r) * K + k0);
            const uint4* sl = (const uint4*)(Bl + (size_t)(bn + r) * K + k0);
            *(uint4*)(sBh + r*GPAD + c8*8) = sh[c8];
            *(uint4*)(sBl + r*GPAD + c8*8) = sl[c8];
        }
        __syncthreads();

        #pragma unroll
        for (int kk = 0; kk < 4; kk++) {
            wmma::fragment<wmma::matrix_a, 16, 16, 16, __nv_bfloat16, wmma::row_major> aH[2], aL[2];
            wmma::fragment<wmma::matrix_b, 16, 16, 16, __nv_bfloat16, wmma::col_major> bH[2], bL[2];
            #pragma unroll
            for (int mi = 0; mi < 2; mi++) {
                const __nv_bfloat16* pa = sAh + (wm*32 + mi*16)*GPAD + kk*16;
                const __nv_bfloat16* pl = sAl + (wm*32 + mi*16)*GPAD + kk*16;
                wmma::load_matrix_sync(aH[mi], pa, GPAD);
                wmma::load_matrix_sync(aL[mi], pl, GPAD);
            }
            #pragma unroll
            for (int ni = 0; ni < 2; ni++) {
                const __nv_bfloat16* pb = sBh + (wn*32 + ni*16)*GPAD + kk*16;
                const __nv_bfloat16* pl = sBl + (wn*32 + ni*16)*GPAD + kk*16;
                wmma::load_matrix_sync(bH[ni], pb, GPAD);
                wmma::load_matrix_sync(bL[ni], pl, GPAD);
            }
            #pragma unroll
            for (int mi = 0; mi < 2; mi++)
                #pragma unroll
                for (int ni = 0; ni < 2; ni++) {
                    wmma::mma_sync(acc[mi][ni], aH[mi], bH[ni], acc[mi][ni]);
                    wmma::mma_sync(acc[mi][ni], aH[mi], bL[ni], acc[mi][ni]);
                    wmma::mma_sync(acc[mi][ni], aL[mi], bH[ni], acc[mi][ni]);
                }
        }
        __syncthreads();
    }

    // epilogue via smem (128 x 64, stride 68)
    #pragma unroll
    for (int mi = 0; mi < 2; mi++)
        #pragma unroll
        for (int ni = 0; ni < 2; ni++)
            wmma::store_matrix_sync(sC + (wm*32 + mi*16)*68 + wn*32 + ni*16,
                                    acc[mi][ni], 68, wmma::mem_row_major);
    __syncthreads();
    #pragma unroll
    for (int q = 0; q < 8; q++) {
        int j = q * 256 + tid;
        int r = j >> 4, c4 = (j & 15) * 4;
        float4 v = *(float4*)(sC + r*68 + c4);
        float4 b = *(const float4*)(bias + bn + c4);
        v.x += b.x; v.y += b.y; v.z += b.z; v.w += b.w;
        *(float4*)(C + (size_t)(bm + r) * N + bn + c4) = v;
    }
}

// ---------------- kernel CR: char GRU recurrent (WhT fully in smem) ----------
#define CR_WPB 16
__global__ __launch_bounds__(256, 1)
void k_charrec(const float* __restrict__ cbh) {
    extern __shared__ float sm[];
    float* sW = sm;                      // [128][384]
    float* sH = sm + CHID*G3C;           // [16][128]
    const int tid = threadIdx.x;
    const int j = tid & 127;
    const int half = tid >> 7;
    const int n0 = blockIdx.x * CR_WPB;

    {
        const float4* src = (const float4*)g_WhT;
        float4* dst = (float4*)sW;
        for (int i = tid; i < CHID*G3C/4; i += 256) dst[i] = src[i];
        float4 z4 = make_float4(0.f,0.f,0.f,0.f);
        float4* h4 = (float4*)sH;
        for (int i = tid; i < CR_WPB*CHID/4; i += 256) h4[i] = z4;
    }
    const float bR = cbh[j], bZ = cbh[CHID + j], bN = cbh[2*CHID + j];
    __syncthreads();

    for (int t = 0; t < LLC; t++) {
        float xr[8], xz[8], xn[8];
        #pragma unroll
        for (int q = 0; q < 8; q++) {
            size_t rr = ((size_t)(n0 + half*8 + q)*LLC + t)*G3C;
            xr[q] = g_cxw[rr + j];
            xz[q] = g_cxw[rr + CHID + j];
            xn[q] = g_cxw[rr + 2*CHID + j];
        }
        float aR[8], aZ[8], aN[8];
        #pragma unroll
        for (int q = 0; q < 8; q++) { aR[q]=bR; aZ[q]=bZ; aN[q]=bN; }

        #pragma unroll 2
        for (int i = 0; i < CHID; i++) {
            float wr = sW[i*G3C + j];
            float wz = sW[i*G3C + CHID + j];
            float wn = sW[i*G3C + 2*CHID + j];
            const float* hrow = sH + half*8*CHID + i;
            #pragma unroll
            for (int q = 0; q < 8; q++) {
                float hv = hrow[q*CHID];
                aR[q] = fmaf(hv, wr, aR[q]);
                aZ[q] = fmaf(hv, wz, aZ[q]);
                aN[q] = fmaf(hv, wn, aN[q]);
            }
        }
        __syncthreads();
        #pragma unroll
        for (int q = 0; q < 8; q++) {
            int w = half*8 + q;
            float r  = 1.f / (1.f + expf(-(xr[q] + aR[q])));
            float z  = 1.f / (1.f + expf(-(xz[q] + aZ[q])));
            float nn = tanhf(xn[q] + r*aN[q]);
            float hp = sH[w*CHID + j];
            sH[w*CHID + j] = nn + z*(hp - nn);
        }
        __syncthreads();
    }
    #pragma unroll
    for (int q = 0; q < 8; q++) {
        int w = half*8 + q;
        g_charh[(size_t)(n0 + w)*CHID + j] = sH[w*CHID + j];
    }
}

// ---------------- persistent word GRU ----------------
__device__ __forceinline__ void grid_barrier() {
    __threadfence();
    __syncthreads();
    if (threadIdx.x == 0) {
        volatile unsigned int* vph = &g_barPhase;
        unsigned int ph = *vph;
        unsigned int a = atomicAdd(&g_barArrive, 1u);
        if (a == NBLK_W - 1u) {
            g_barArrive = 0u;
            __threadfence();
            *vph = ph + 1u;
        } else {
            while (*vph == ph) { __nanosleep(20); }
        }
        __threadfence();
    }
    __syncthreads();
}

__device__ __forceinline__ float dot4(float4 a, float4 b, float c) {
    c = fmaf(a.x, b.x, c); c = fmaf(a.y, b.y, c);
    c = fmaf(a.z, b.z, c); c = fmaf(a.w, b.w, c);
    return c;
}

#define WBB 32
#define WJB 16
#define WST 516

__global__ __launch_bounds__(128, 1)
void k_wordgru(const float* __restrict__ gWh, const float* __restrict__ gbh) {
    extern __shared__ float sm[];
    float* sW = sm;                 // [48][516]
    float* sH = sm + 48*WST;        // [32][512]
    const int tid = threadIdx.x;
    const int bid = blockIdx.x;
    const int jc = bid & 31, bc = bid >> 5;
    const int j0 = jc * WJB, b0 = bc * WBB;
    const int jl = tid & 15;
    const int bq = tid >> 4;
    const int bl0 = bq * 4;

    for (int i = tid; i < 48*HID; i += 128) {
        int gl = i >> 9, k = i & 511;
        int gate = gl >> 4, jj = gl & 15;
        int g = gate*HID + j0 + jj;
        sW[gl*WST + k] = gWh[(size_t)g*HID + k];
    }
    const float bhR = gbh[j0 + jl];
    const float bhZ = gbh[HID + j0 + jl];
    const float bhN = gbh[2*HID + j0 + jl];
    {
        float4 z4 = make_float4(0.f,0.f,0.f,0.f);
        float4* h4 = (float4*)sH;
        for (int i = tid; i < WBB*HID/4; i += 128) h4[i] = z4;
    }
    __syncthreads();

    const float4* wR = (const float4*)(sW + (0*16 + jl)*WST);
    const float4* wZ = (const float4*)(sW + (16  + jl)*WST);
    const float4* wN = (const float4*)(sW + (32  + jl)*WST);
    const int j = j0 + jl;

    for (int s = 0; s < SSQ; s++) {
        float xr[4], xz[4], xn[4];
        #pragma unroll
        for (int q = 0; q < 4; q++) {
            size_t base = ((size_t)(b0 + bl0 + q)*SSQ + s) * G3H;
            xr[q] = g_xw[base + j];
            xz[q] = g_xw[base + HID + j];
            xn[q] = g_xw[base + 2*HID + j];
        }

        float aR[4], aZ[4], aNh[4];
        #pragma unroll
        for (int q = 0; q < 4; q++) { aR[q]=bhR; aZ[q]=bhZ; aNh[q]=bhN; }

        const float4* h0p = (const float4*)(sH + (bl0+0)*HID);
        const float4* h1p = (const float4*)(sH + (bl0+1)*HID);
        const float4* h2p = (const float4*)(sH + (bl0+2)*HID);
        const float4* h3p = (const float4*)(sH + (bl0+3)*HID);
        #pragma unroll 4
        for (int k4 = 0; k4 < HID/4; k4++) {
            float4 r4 = wR[k4], z4 = wZ[k4], n4 = wN[k4];
            float4 h0 = h0p[k4], h1 = h1p[k4], h2 = h2p[k4], h3 = h3p[k4];
            aR[0]=dot4(h0,r4,aR[0]); aZ[0]=dot4(h0,z4,aZ[0]); aNh[0]=dot4(h0,n4,aNh[0]);
            aR[1]=dot4(h1,r4,aR[1]); aZ[1]=dot4(h1,z4,aZ[1]); aNh[1]=dot4(h1,n4,aNh[1]);
            aR[2]=dot4(h2,r4,aR[2]); aZ[2]=dot4(h2,z4,aZ[2]); aNh[2]=dot4(h2,n4,aNh[2]);
            aR[3]=dot4(h3,r4,aR[3]); aZ[3]=dot4(h3,z4,aZ[3]); aNh[3]=dot4(h3,n4,aNh[3]);
        }

        float* hOut = g_hword + ((s + 1) & 1) * (BB*HID);
        #pragma unroll
        for (int q = 0; q < 4; q++) {
            int b = b0 + bl0 + q;
            float r  = 1.f / (1.f + expf(-(xr[q] + aR[q])));
            float z  = 1.f / (1.f + expf(-(xz[q] + aZ[q])));
            float nn = tanhf(xn[q] + r*aNh[q]);
            float hp = sH[(bl0+q)*HID + j];
            float hn = nn + z*(hp - nn);
            hOut[b*HID + j] = hn;
            g_gruout[((size_t)b*SSQ + s)*HID + j] = hn;
        }
        if (s == SSQ - 1) break;
        grid_barrier();
        const float4* hIn4 = (const float4*)(g_hword + ((s + 1) & 1) * (BB*HID) + b0*HID);
        float4* sH4 = (float4*)sH;
        for (int i = tid; i < WBB*HID/4; i += 128) sH4[i] = hIn4[i];
        __syncthreads();
    }
}

// ---------------- classifier ----------------
__global__ __launch_bounds__(256)
void k_cls(const float* __restrict__ clsW, const float* __restrict__ clsb,
           float* __restrict__ out) {
    const int warp = threadIdx.x >> 5, lane = threadIdx.x & 31;
    const int gw = blockIdx.x * 8 + warp;
    for (int row = gw; row < NW; row += gridDim.x * 8) {
        const float* hrow = g_gruout + (size_t)row * HID;
        float acc[NCLS];
        #pragma unroll
        for (int c = 0; c < NCLS; c++) acc[c] = 0.f;
        for (int k = lane; k < HID; k += 32) {
            float hv = hrow[k];
            #pragma unroll
            for (int c = 0; c < NCLS; c++)
                acc[c] = fmaf(hv, clsW[c*HID + k], acc[c]);
        }
        #pragma unroll
        for (int off = 16; off > 0; off >>= 1) {
            #pragma unroll
            for (int c = 0; c < NCLS; c++)
                acc[c] += __shfl_down_sync(0xffffffffu, acc[c], off);
        }
        if (lane == 0) {
            #pragma unroll
            for (int c = 0; c < NCLS; c++)
                out[(size_t)row*NCLS + c] = acc[c] + clsb[c];
        }
    }
}

// ---------------- launch ----------------
extern "C" void kernel_launch(void* const* d_in, const int* in_sizes, int n_in,
                              void* d_out, int out_size) {
    const int*   x     = (const int*)  d_in[0];
    const int*   xch   = (const int*)  d_in[1];
    const float* embw  = (const float*)d_in[2];
    const float* cembw = (const float*)d_in[3];
    const float* cWi   = (const float*)d_in[4];
    const float* cWh   = (const float*)d_in[5];
    const float* cbi   = (const float*)d_in[6];
    const float* cbh   = (const float*)d_in[7];
    const float* gWi   = (const float*)d_in[8];
    const float* gWh   = (const float*)d_in[9];
    const float* gbi   = (const float*)d_in[10];
    const float* gbh   = (const float*)d_in[11];
    const float* clsW  = (const float*)d_in[12];
    const float* clsb  = (const float*)d_in[13];
    float* out = (float*)d_out;

    // device-symbol addresses for GEMM args
    void *aCh, *aCl, *aXh, *aXl, *bCh, *bCl, *bXh, *bXl;
    cudaGetSymbolAddress(&aCh, g_AcH);  cudaGetSymbolAddress(&aCl, g_AcL);
    cudaGetSymbolAddress(&aXh, g_AxH);  cudaGetSymbolAddress(&aXl, g_AxL);
    cudaGetSymbolAddress(&bCh, g_BcxHi); cudaGetSymbolAddress(&bCl, g_BcxLo);
    cudaGetSymbolAddress(&bXh, g_BxwHi); cudaGetSymbolAddress(&bXl, g_BxwLo);
    void *pcxw, *pxw;
    cudaGetSymbolAddress(&pcxw, g_cxw);
    cudaGetSymbolAddress(&pxw, g_xw);

    const int crsmem = (CHID*G3C + CR_WPB*CHID) * 4;
    const int wsmem  = (48*WST + WBB*HID) * 4;
    cudaFuncSetAttribute(k_charrec, cudaFuncAttributeMaxDynamicSharedMemorySize, crsmem);
    cudaFuncSetAttribute(k_wordgru, cudaFuncAttributeMaxDynamicSharedMemorySize, wsmem);
    cudaFuncSetAttribute(k_gemm,    cudaFuncAttributeMaxDynamicSharedMemorySize, GEMM_SMEM);

    k_prep<<<512, 256>>>(cWh, gWi, cWi);
    k_gatherA_c<<<NW*LLC/256, 256>>>(xch, cembw);
    dim3 gc(G3C/64, NW*LLC/128);   // (6, 4096)
    k_gemm<<<gc, 256, GEMM_SMEM>>>((const __nv_bfloat16*)aCh, (const __nv_bfloat16*)aCl,
                                   (const __nv_bfloat16*)bCh, (const __nv_bfloat16*)bCl,
                                   cbi, (float*)pcxw, G3C, CEMB);
    k_charrec<<<NW/CR_WPB, 256, crsmem>>>(cbh);
    k_gatherA_x<<<NW/8, 256>>>(x, embw);
    dim3 gx(G3H/64, NW/128);       // (24, 256)
    k_gemm<<<gx, 256, GEMM_SMEM>>>((const __nv_bfloat16*)aXh, (const __nv_bfloat16*)aXl,
                                   (const __nv_bfloat16*)bXh, (const __nv_bfloat16*)bXl,
                                   gbi, (float*)pxw, G3H, DIM);
    k_wordgru<<<NBLK_W, 128, wsmem>>>(gWh, gbh);
    k_cls<<<512, 256>>>(clsW, clsb, out);
}